// round 10
// baseline (speedup 1.0000x reference)
#include <cuda_runtime.h>
#include <cuda_fp16.h>
#include <cstdint>

// ---------------------------------------------------------------------------
// MixedLayerWithArc: per-sample branch-selected 3x3 conv as implicit GEMM,
// mma.sync.m16n8k16 fp16 (fp32 accum), TAP-MAJOR K (k = tap*256 + ci).
//
// R8: CTA = 256co x 128pix (fused co-tiles -> im2col built once per pixel
// tile), 512 threads / 16 warps (warp tile 64x32), 3-stage single-barrier
// pipeline (3x A + 3x B smem buffers, cp.async depth 2).
// ---------------------------------------------------------------------------

static constexpr int KTOT = 2304;                   // 9 taps * 256 ci
static constexpr int NCH  = KTOT / 64;              // 36 chunks of BK=64
static constexpr int STAGE_BYTES = 49152;           // A 32KB + B 16KB
static constexpr int SMEM_BYTES  = 1024 + 3 * STAGE_BYTES;

// fp16 tap-major weights: [4][256co][9tap][256ci]
__device__ __align__(16) __half g_Wh[4 * 256 * 2304];

#define SWZ(o) ((o) ^ (((o) >> 3) & 0x70))

__device__ __forceinline__ uint32_t smem_u32(const void* p) {
    uint32_t a;
    asm("{ .reg .u64 t; cvta.to.shared.u64 t, %1; cvt.u32.u64 %0, t; }"
        : "=r"(a) : "l"(p));
    return a;
}
__device__ __forceinline__ uint32_t pack_h2(float lo, float hi) {
    uint32_t u;
    asm("cvt.rn.f16x2.f32 %0, %1, %2;" : "=r"(u) : "f"(hi), "f"(lo));
    return u;
}
__device__ __forceinline__ void cp16(uint32_t dst, const void* src) {
    asm volatile("cp.async.cg.shared.global [%0], [%1], 16;"
                 :: "r"(dst), "l"(src) : "memory");
}
__device__ __forceinline__ void sts128(uint32_t a, uint32_t v0, uint32_t v1,
                                       uint32_t v2, uint32_t v3) {
    asm volatile("st.shared.v4.b32 [%0], {%1,%2,%3,%4};"
                 :: "r"(a), "r"(v0), "r"(v1), "r"(v2), "r"(v3) : "memory");
}
__device__ __forceinline__ void ldsm4(uint32_t& r0, uint32_t& r1, uint32_t& r2,
                                      uint32_t& r3, uint32_t a) {
    asm volatile("ldmatrix.sync.aligned.m8n8.x4.shared.b16 {%0,%1,%2,%3}, [%4];"
                 : "=r"(r0), "=r"(r1), "=r"(r2), "=r"(r3) : "r"(a));
}
__device__ __forceinline__ void mma16(float* c, const uint32_t* a,
                                      uint32_t b0, uint32_t b1) {
    asm volatile(
        "mma.sync.aligned.m16n8k16.row.col.f32.f16.f16.f32 "
        "{%0,%1,%2,%3}, {%4,%5,%6,%7}, {%8,%9}, {%0,%1,%2,%3};"
        : "+f"(c[0]), "+f"(c[1]), "+f"(c[2]), "+f"(c[3])
        : "r"(a[0]), "r"(a[1]), "r"(a[2]), "r"(a[3]), "r"(b0), "r"(b1));
}

// Pre-pass: W [arc*co][ci][tap] f32 -> g_Wh [arc*co][tap][ci] fp16.
__global__ void cvt_w_kernel(const float* __restrict__ W) {
    const int o    = blockIdx.x * 256 + threadIdx.x;
    const int ci   = o & 255;
    const int r    = o >> 8;            // (arc*256+co)*9 + tap
    const int tap  = r - (r / 9) * 9;
    const int acoc = r / 9;
    g_Wh[o] = __float2half_rn(W[(acoc * 256 + ci) * 9 + tap]);
}

__global__ void __launch_bounds__(512, 1)
mixed_conv_kernel(const float* __restrict__ x, const int* __restrict__ arcp,
                  const float* __restrict__ bias, float* __restrict__ out)
{
    extern __shared__ __align__(16) char smem_raw[];
    const uint32_t base = (smem_u32(smem_raw) + 1023) & ~1023u;
    uint32_t sA[3], sB[3];
    #pragma unroll
    for (int st = 0; st < 3; st++) {
        sA[st] = base + st * STAGE_BYTES;
        sB[st] = base + st * STAGE_BYTES + 32768;
    }

    const int tid = threadIdx.x;
    const int wid = tid >> 5, lid = tid & 31;
    const int wm  = wid >> 2;            // 0..3 -> 64 co rows
    const int wn  = wid & 3;             // 0..3 -> 32 pixel cols
    const int bid = blockIdx.x;
    const int b   = bid >> 3;
    const int n0  = (bid & 7) * 128;
    const int arc = __ldg(arcp + b);

    const float*  xb = x + (size_t)b * 262144;                 // 256*1024
    const __half* Wb = g_Wh + (size_t)arc * (256 * 2304);      // all 256 co

    // B-fill geometry: thread t -> pixel p = t&127, k-quarter (16 ci) = t>>7
    const int p  = tid & 127;
    const int kq = tid >> 7;             // 0..3
    const int pg = n0 + p;
    const int h  = pg >> 5;
    const int w  = pg & 31;

    // ldmatrix per-lane decomposition (validated in R4/R7 kernels)
    const int rsubA = lid & 15;
    const int csubA = ((lid >> 4) & 1) * 16;
    const int rsubB = (lid & 7) + ((lid >> 4) & 1) * 8;
    const int csubB = ((lid >> 3) & 1) * 16;
    int rowA[4], rselA[4], rowB[2], rselB[2];
    #pragma unroll
    for (int mi = 0; mi < 4; mi++) {
        rowA[mi]  = wm * 64 + mi * 16 + rsubA;
        rselA[mi] = (rowA[mi] & 7) << 4;
    }
    #pragma unroll
    for (int jj = 0; jj < 2; jj++) {
        rowB[jj]  = wn * 32 + jj * 16 + rsubB;
        rselB[jj] = (rowB[jj] & 7) << 4;
    }

    float acc[4][4][4];                  // [mi][n8][quad]
    #pragma unroll
    for (int mi = 0; mi < 4; mi++)
        #pragma unroll
        for (int ni = 0; ni < 4; ni++)
            #pragma unroll
            for (int e = 0; e < 4; e++) acc[mi][ni][e] = 0.0f;

    // ---- helpers ------------------------------------------------------------
    auto issueA = [&](int chunk, int st) {      // 256x64 fp16 tile via cp.async
        #pragma unroll
        for (int m = 0; m < 4; m++) {
            const int c = tid + 512 * m;        // 2048 16B units
            const int r = c >> 3, q = c & 7;
            cp16(sA[st] + SWZ(r * 128 + q * 16),
                 Wb + (size_t)r * 2304 + chunk * 64 + q * 8);
        }
    };
    auto loadB = [&](int chunk, uint32_t* u) {  // 16 ci values -> 8 half2
        const int tap = chunk >> 2;             // 4 chunks per tap
        const int dh  = tap / 3 - 1;
        const int dw  = tap - (dh + 1) * 3 - 1;
        const bool ok = ((unsigned)(h + dh) < 32u) && ((unsigned)(w + dw) < 32u);
        const float* src = xb + ((chunk & 3) * 64 + kq * 16) * 1024
                              + (h + dh) * 32 + (w + dw);
        #pragma unroll
        for (int j = 0; j < 8; j++) {
            const float v0 = ok ? __ldg(src + (2 * j)     * 1024) : 0.0f;
            const float v1 = ok ? __ldg(src + (2 * j + 1) * 1024) : 0.0f;
            u[j] = pack_h2(v0, v1);
        }
    };
    auto storeB = [&](const uint32_t* u, int st) {  // 2x STS.128
        const uint32_t off = p * 128 + kq * 32;
        sts128(sB[st] + SWZ(off),      u[0], u[1], u[2], u[3]);
        sts128(sB[st] + SWZ(off + 16), u[4], u[5], u[6], u[7]);
    };

    // ---- prologue: stage chunks 0 and 1 ------------------------------------
    issueA(0, 0);
    asm volatile("cp.async.commit_group;" ::: "memory");
    issueA(1, 1);
    asm volatile("cp.async.commit_group;" ::: "memory");
    {
        uint32_t u0[8];
        loadB(0, u0); storeB(u0, 0);
        loadB(1, u0); storeB(u0, 1);
    }

    // ---- main loop: one barrier per chunk -----------------------------------
    for (int i = 0; i < NCH; i++) {
        const int st = i - (i / 3) * 3;          // i % 3
        // retire A group for stage st (leave the newer one in flight)
        if (i < NCH - 1)
            asm volatile("cp.async.wait_group 1;" ::: "memory");
        else
            asm volatile("cp.async.wait_group 0;" ::: "memory");
        __syncthreads();   // all warps done with iter i-1; A[st]/B[st] ready

        uint32_t u[8];
        const int pf = i + 2;
        const int pst = pf - (pf / 3) * 3;
        if (pf < NCH) {
            issueA(pf, pst);                     // safe: buffer last read i-1
            asm volatile("cp.async.commit_group;" ::: "memory");
            loadB(pf, u);                        // LDG latency hidden by compute
        }

        const uint32_t sAb = sA[st], sBb = sB[st];
        #pragma unroll
        for (int ks = 0; ks < 4; ks++) {         // 4 x k16 steps
            uint32_t a[4][4];
            #pragma unroll
            for (int mi = 0; mi < 4; mi++)
                ldsm4(a[mi][0], a[mi][1], a[mi][2], a[mi][3],
                      sAb + rowA[mi] * 128 + ((ks * 32 + csubA) ^ rselA[mi]));
            #pragma unroll
            for (int jj = 0; jj < 2; jj++) {
                uint32_t b0, b1, b2, b3;
                ldsm4(b0, b1, b2, b3,
                      sBb + rowB[jj] * 128 + ((ks * 32 + csubB) ^ rselB[jj]));
                #pragma unroll
                for (int mi = 0; mi < 4; mi++) {
                    mma16(acc[mi][2 * jj + 0], a[mi], b0, b1);
                    mma16(acc[mi][2 * jj + 1], a[mi], b2, b3);
                }
            }
        }
        if (pf < NCH) storeB(u, pst);            // safe: buffer last read i-1
    }

    // ---- epilogue: bias + store --------------------------------------------
    const int g = lid >> 2, t = lid & 3;
    #pragma unroll
    for (int mi = 0; mi < 4; mi++) {
        const int r0 = wm * 64 + mi * 16 + g;          // co of c0/c1
        const float bv0 = __ldg(bias + arc * 256 + r0);
        const float bv1 = __ldg(bias + arc * 256 + r0 + 8);
        float* o0 = out + ((size_t)(b * 256 + r0)) * 1024 + n0 + wn * 32 + 2 * t;
        float* o1 = o0 + 8 * 1024;
        #pragma unroll
        for (int ni = 0; ni < 4; ni++) {
            float2 v0 = { acc[mi][ni][0] + bv0, acc[mi][ni][1] + bv0 };
            float2 v1 = { acc[mi][ni][2] + bv1, acc[mi][ni][3] + bv1 };
            *reinterpret_cast<float2*>(o0 + ni * 8) = v0;
            *reinterpret_cast<float2*>(o1 + ni * 8) = v1;
        }
    }
}

extern "C" void kernel_launch(void* const* d_in, const int* in_sizes, int n_in,
                              void* d_out, int out_size) {
    const float* x    = (const float*)d_in[0];   // [64,256,32,32]
    const int*   arc  = (const int*)d_in[1];     // [64]
    const float* W    = (const float*)d_in[2];   // [4,256,256,3,3]
    const float* bias = (const float*)d_in[3];   // [4,256]
    float* out = (float*)d_out;                  // [64,256,32,32]
    (void)in_sizes; (void)n_in; (void)out_size;

    // 4*256*2304 = 2,359,296 elements / 256 threads = 9216 blocks
    cvt_w_kernel<<<9216, 256>>>(W);

    cudaFuncSetAttribute(mixed_conv_kernel,
                         cudaFuncAttributeMaxDynamicSharedMemorySize, SMEM_BYTES);
    // 64 samples x 8 pixel-tiles (full 256 co per CTA)
    mixed_conv_kernel<<<512, 512, SMEM_BYTES>>>(x, arc, bias, out);
}